// round 7
// baseline (speedup 1.0000x reference)
#include <cuda_runtime.h>
#include <cuda_bf16.h>
#include <cstdint>

#define THREADS 256
#define NCHUNKS_TOT 288          // L0:32  L1:128  L2:128

// A in mma-fragment-linear layout:
// uint4 index = ((chunk*8 + mtrole)*8 + q)*32 + lane,  q = ks*4 + mh*2 + term
__device__ __align__(16) uint4 g_Wfrag[(size_t)NCHUNKS_TOT * 8 * 8 * 32];

// ---- SMEM layout (bytes), per 256-thread CTA (1 batch) ----
#define BBUF_OFF 0                 // 4 x 8192 (ring)
#define XS_OFF   32768             // 32 x 65 x 4  = 8320
#define HS_OFF   41088             // 128 x 65 x 4 = 33280
#define RED_OFF  74368             // 8 floats
#define SMEM_BYTES (RED_OFF + 64)

__device__ __forceinline__ uint32_t smem_u32(const void* p) {
    uint32_t a;
    asm("{ .reg .u64 t; cvta.to.shared.u64 t, %1; cvt.u32.u64 %0, t; }" : "=r"(a) : "l"(p));
    return a;
}
__device__ __forceinline__ uint32_t sw128(uint32_t o) { return o ^ ((o >> 3) & 0x70); }
__device__ __forceinline__ uint32_t pkbf(float a, float b) {
    __nv_bfloat16 ha = __float2bfloat16(a), hb = __float2bfloat16(b);
    return (uint32_t)__bfloat16_as_ushort(ha) | ((uint32_t)__bfloat16_as_ushort(hb) << 16);
}
__device__ __forceinline__ void ldsm4(uint32_t* r, uint32_t addr) {
    asm volatile("ldmatrix.sync.aligned.m8n8.x4.shared.b16 {%0,%1,%2,%3}, [%4];"
                 : "=r"(r[0]), "=r"(r[1]), "=r"(r[2]), "=r"(r[3]) : "r"(addr));
}
__device__ __forceinline__ void mma16816_u4(float* c, const uint4& a, const uint32_t* b) {
    asm volatile("mma.sync.aligned.m16n8k16.row.col.f32.bf16.bf16.f32 "
                 "{%0,%1,%2,%3}, {%4,%5,%6,%7}, {%8,%9}, {%0,%1,%2,%3};"
                 : "+f"(c[0]), "+f"(c[1]), "+f"(c[2]), "+f"(c[3])
                 : "r"(a.x), "r"(a.y), "r"(a.z), "r"(a.w), "r"(b[0]), "r"(b[1]));
}
__device__ __forceinline__ uint32_t pk_term(float v0, float v1, int term) {
    if (term == 0) return pkbf(v0, v1);
    const __nv_bfloat16 h0 = __float2bfloat16(v0), h1 = __float2bfloat16(v1);
    return pkbf(v0 - __bfloat162float(h0), v1 - __bfloat162float(h1));
}

// ---------------- pre-pass: write A fragments ----------------
__global__ __launch_bounds__(512) void prep_kernel(
    const float* __restrict__ W0, const float* __restrict__ W1, const float* __restrict__ W2)
{
    const int g = blockIdx.x;
    const float* W; int kbase;
    if (g < 32)       { W = W0; kbase = g * 32; }
    else if (g < 160) { W = W1; kbase = (g - 32) * 32; }
    else              { W = W2; kbase = (g - 160) * 32; }

    #pragma unroll
    for (int i = 0; i < 4; ++i) {
        const int idx  = threadIdx.x + i * 512;   // 0..2047
        const int lane = idx & 31;
        const int q    = (idx >> 5) & 7;
        const int mt   = idx >> 8;                // warp role 0..7
        const int ks   = q >> 2, mh = (q >> 1) & 1, term = q & 1;
        const int r    = mt * 32 + mh * 16 + (lane >> 2);
        const int k0   = ks * 16 + (lane & 3) * 2;

        const float w00 = W[(size_t)(kbase + k0)     * 256 + r];
        const float w01 = W[(size_t)(kbase + k0 + 1) * 256 + r];
        const float w10 = W[(size_t)(kbase + k0 + 8) * 256 + r];
        const float w11 = W[(size_t)(kbase + k0 + 9) * 256 + r];
        const float v00 = W[(size_t)(kbase + k0)     * 256 + r + 8];
        const float v01 = W[(size_t)(kbase + k0 + 1) * 256 + r + 8];
        const float v10 = W[(size_t)(kbase + k0 + 8) * 256 + r + 8];
        const float v11 = W[(size_t)(kbase + k0 + 9) * 256 + r + 8];

        uint4 o;
        o.x = pk_term(w00, w01, term);
        o.y = pk_term(v00, v01, term);
        o.z = pk_term(w10, w11, term);
        o.w = pk_term(v10, v11, term);
        g_Wfrag[((size_t)g * 8 + mt) * 256 + q * 32 + lane] = o;
    }
}

// ---------------- main kernel: 1 batch per CTA, 2 CTAs/SM, 4-deep B ring ----------------
__global__ __launch_bounds__(THREADS, 2) void cin_mma_kernel(
    const float* __restrict__ x,
    const float* __restrict__ b0, const float* __restrict__ b1, const float* __restrict__ b2,
    const float* __restrict__ fcW, const float* __restrict__ fcb,
    float* __restrict__ out)
{
    extern __shared__ unsigned char smem[];
    const uint32_t sbase = smem_u32(smem);
    float* xs  = (float*)(smem + XS_OFF);
    float* hs  = (float*)(smem + HS_OFF);
    float* red = (float*)(smem + RED_OFF);

    const int tid = threadIdx.x, wid = tid >> 5, lane = tid & 31;
    const int B = blockIdx.x;
    const int mt = wid;

    // B ldmatrix lane addressing
    const int brl  = ((lane >> 4) << 3) + (lane & 7);
    const int bk16 = ((lane >> 3) & 1) * 16;

    // z-build mapping
    const int brow = tid >> 2;
    const int seg  = (tid & 3) * 8;
    const float* xvb = xs + brow;
    const float* biasl[3] = {b0, b1, b2};

    // stage x into padded xs (stride 65)
    #pragma unroll
    for (int i = 0; i < 2; ++i) {
        const int idx = tid + i * 256;
        const float4 v = ((const float4*)(x + (size_t)B * 2048))[idx];
        const int f = idx * 4;
        float* dp = xs + (f >> 6) * 65 + (f & 63);
        dp[0] = v.x; dp[1] = v.y; dp[2] = v.z; dp[3] = v.w;
    }
    __syncthreads();

    float fc_acc = 0.0f;
    const int r0 = lane >> 2;

    for (int layer = 0; layer < 3; ++layer) {
        const int nch = (layer == 0) ? 32 : 128;
        const int g0  = (layer == 0) ? 0 : ((layer == 1) ? 32 : 160);
        const float* hvb = (layer == 0) ? (xs + brow) : (hs + brow);

        float acc[2][8][4];
        #pragma unroll
        for (int a = 0; a < 2; ++a)
            #pragma unroll
            for (int j = 0; j < 8; ++j)
                #pragma unroll
                for (int e = 0; e < 4; ++e) acc[a][j][e] = 0.0f;

        auto buildB = [&](int cc, int buf) {
            const int m  = (layer == 0) ? cc : (cc >> 2);
            const int nb = (layer == 0) ? 0 : ((cc & 3) * 32);
            const float xv = xvb[m * 65];
            uint32_t hpk[4], lpk[4];
            #pragma unroll
            for (int q = 0; q < 4; ++q) {
                const float p0 = xv * hvb[(nb + seg + 2 * q) * 65];
                const float p1 = xv * hvb[(nb + seg + 2 * q + 1) * 65];
                const __nv_bfloat16 h0 = __float2bfloat16(p0), h1 = __float2bfloat16(p1);
                hpk[q] = (uint32_t)__bfloat16_as_ushort(h0) |
                         ((uint32_t)__bfloat16_as_ushort(h1) << 16);
                lpk[q] = pkbf(p0 - __bfloat162float(h0), p1 - __bfloat162float(h1));
            }
            unsigned char* bbs = smem + BBUF_OFF + buf * 8192;
            const uint32_t offh = brow * 128 + seg * 2;
            *(uint4*)(bbs + sw128(offh))      = make_uint4(hpk[0], hpk[1], hpk[2], hpk[3]);
            *(uint4*)(bbs + sw128(offh + 64)) = make_uint4(lpk[0], lpk[1], lpk[2], lpk[3]);
        };

        auto chunkStep = [&](int c, int nchl) {
            // A fragments for chunk c (L2/L1 resident)
            const uint4* __restrict__ P =
                g_Wfrag + ((size_t)(g0 + c) * 8 + mt) * 256 + lane;
            uint4 Aq[8];
            #pragma unroll
            for (int q = 0; q < 8; ++q) Aq[q] = P[q * 32];

            // build 2 chunks ahead (ring slot (c+2)&3, protected by last barrier)
            if (c + 2 < nchl) buildB(c + 2, (c + 2) & 3);

            const uint32_t bbse = sbase + BBUF_OFF + (c & 3) * 8192;
            #pragma unroll
            for (int ks = 0; ks < 2; ++ks) {
                #pragma unroll
                for (int jj = 0; jj < 4; ++jj) {
                    const uint32_t boff = (uint32_t)(jj * 16 + brl) * 128 + 32 * ks + bk16;
                    uint32_t Bh[4], Bl[4];
                    ldsm4(Bh, bbse + sw128(boff));
                    ldsm4(Bl, bbse + sw128(boff + 64));
                    #pragma unroll
                    for (int mh = 0; mh < 2; ++mh) {
                        #pragma unroll
                        for (int jq = 0; jq < 2; ++jq) {
                            float* cc2 = acc[mh][2 * jj + jq];
                            mma16816_u4(cc2, Aq[ks * 4 + mh * 2 + 0], Bh + 2 * jq);  // hi*hi
                            mma16816_u4(cc2, Aq[ks * 4 + mh * 2 + 0], Bl + 2 * jq);  // hi*lo
                            mma16816_u4(cc2, Aq[ks * 4 + mh * 2 + 1], Bh + 2 * jq);  // lo*hi
                        }
                    }
                }
            }
        };

        buildB(0, 0);
        buildB(1, 1);
        __syncthreads();

        for (int c = 0; c < nch; c += 2) {
            chunkStep(c, nch);       // builds c+2 into (c+2)&3
            chunkStep(c + 1, nch);   // builds c+3 into (c+3)&3
            __syncthreads();         // publish builds; release slots read this iter
        }

        // ---- epilogue ----
        const float* bl = biasl[layer];
        const int fcbase = (layer == 2) ? 256 : layer * 128;
        const bool do_fc = (layer == 2) || (mt < 4);
        float bias4[4], fw4[4];
        #pragma unroll
        for (int rr = 0; rr < 4; ++rr) {
            const int row = mt * 32 + rr * 8 + r0;
            bias4[rr] = bl[row];
            fw4[rr] = do_fc ? fcW[fcbase + row] : 0.0f;
        }
        #pragma unroll
        for (int mh = 0; mh < 2; ++mh) {
            #pragma unroll
            for (int j = 0; j < 8; ++j) {
                #pragma unroll
                for (int e = 0; e < 4; ++e) {
                    const int rr = mh * 2 + (e >> 1);
                    const float v = fmaxf(acc[mh][j][e] + bias4[rr], 0.0f);
                    if (do_fc) {
                        fc_acc += fw4[rr] * v;
                    } else {
                        const int row = mt * 32 + mh * 16 + (e >> 1) * 8 + r0;
                        const int d   = 8 * j + 2 * (lane & 3) + (e & 1);
                        hs[(row - 128) * 65 + d] = v;
                    }
                }
            }
        }
        __syncthreads();
    }

    // final reduction (single batch)
    #pragma unroll
    for (int off = 16; off > 0; off >>= 1)
        fc_acc += __shfl_xor_sync(0xffffffffu, fc_acc, off);
    if (lane == 0) red[wid] = fc_acc;
    __syncthreads();
    if (tid == 0) {
        float s = 0.0f;
        #pragma unroll
        for (int w = 0; w < 8; ++w) s += red[w];
        out[B] = s + fcb[0];
    }
}

extern "C" void kernel_launch(void* const* d_in, const int* in_sizes, int n_in,
                              void* d_out, int out_size) {
    const float* x   = (const float*)d_in[0];
    const float* W0  = (const float*)d_in[1];
    const float* b0  = (const float*)d_in[2];
    const float* W1  = (const float*)d_in[3];
    const float* b1  = (const float*)d_in[4];
    const float* W2  = (const float*)d_in[5];
    const float* b2  = (const float*)d_in[6];
    const float* fcW = (const float*)d_in[7];
    const float* fcb = (const float*)d_in[8];
    float* out = (float*)d_out;

    cudaFuncSetAttribute(cin_mma_kernel, cudaFuncAttributeMaxDynamicSharedMemorySize, SMEM_BYTES);
    prep_kernel<<<NCHUNKS_TOT, 512>>>(W0, W1, W2);
    cin_mma_kernel<<<1024, THREADS, SMEM_BYTES>>>(x, b0, b1, b2, fcW, fcb, out);
}

// round 8
// speedup vs baseline: 1.1221x; 1.1221x over previous
#include <cuda_runtime.h>
#include <cuda_bf16.h>
#include <cstdint>

#define THREADS 256
#define NCHUNKS_TOT 288          // L0:32  L1:128  L2:128

// A in mma-fragment-linear layout:
// uint4 index = ((chunk*8 + mtrole)*8 + q)*32 + lane,  q = ks*4 + mh*2 + term
__device__ __align__(16) uint4 g_Wfrag[(size_t)NCHUNKS_TOT * 8 * 8 * 32];

// ---- SMEM layout (bytes), per 256-thread CTA (1 batch) ----
#define BBUF_OFF 0                 // 2 x 8192
#define XS_OFF   16384             // 32 x 65 x 4  = 8320
#define HS_OFF   24704             // 128 x 65 x 4 = 33280
#define RED_OFF  57984             // 8 floats
#define SMEM_BYTES (RED_OFF + 64)

__device__ __forceinline__ uint32_t smem_u32(const void* p) {
    uint32_t a;
    asm("{ .reg .u64 t; cvta.to.shared.u64 t, %1; cvt.u32.u64 %0, t; }" : "=r"(a) : "l"(p));
    return a;
}
__device__ __forceinline__ uint32_t sw128(uint32_t o) { return o ^ ((o >> 3) & 0x70); }
__device__ __forceinline__ uint32_t pkbf(float a, float b) {
    __nv_bfloat16 ha = __float2bfloat16(a), hb = __float2bfloat16(b);
    return (uint32_t)__bfloat16_as_ushort(ha) | ((uint32_t)__bfloat16_as_ushort(hb) << 16);
}
__device__ __forceinline__ void ldsm4(uint32_t* r, uint32_t addr) {
    asm volatile("ldmatrix.sync.aligned.m8n8.x4.shared.b16 {%0,%1,%2,%3}, [%4];"
                 : "=r"(r[0]), "=r"(r[1]), "=r"(r[2]), "=r"(r[3]) : "r"(addr));
}
__device__ __forceinline__ void mma16816_u4(float* c, const uint4& a, const uint32_t* b) {
    asm volatile("mma.sync.aligned.m16n8k16.row.col.f32.bf16.bf16.f32 "
                 "{%0,%1,%2,%3}, {%4,%5,%6,%7}, {%8,%9}, {%0,%1,%2,%3};"
                 : "+f"(c[0]), "+f"(c[1]), "+f"(c[2]), "+f"(c[3])
                 : "r"(a.x), "r"(a.y), "r"(a.z), "r"(a.w), "r"(b[0]), "r"(b[1]));
}
__device__ __forceinline__ uint32_t pk_term(float v0, float v1, int term) {
    if (term == 0) return pkbf(v0, v1);
    const __nv_bfloat16 h0 = __float2bfloat16(v0), h1 = __float2bfloat16(v1);
    return pkbf(v0 - __bfloat162float(h0), v1 - __bfloat162float(h1));
}

// ---------------- pre-pass: write A fragments ----------------
__global__ __launch_bounds__(512) void prep_kernel(
    const float* __restrict__ W0, const float* __restrict__ W1, const float* __restrict__ W2)
{
    const int g = blockIdx.x;
    const float* W; int kbase;
    if (g < 32)       { W = W0; kbase = g * 32; }
    else if (g < 160) { W = W1; kbase = (g - 32) * 32; }
    else              { W = W2; kbase = (g - 160) * 32; }

    #pragma unroll
    for (int i = 0; i < 4; ++i) {
        const int idx  = threadIdx.x + i * 512;   // 0..2047
        const int lane = idx & 31;
        const int q    = (idx >> 5) & 7;
        const int mt   = idx >> 8;                // warp role 0..7
        const int ks   = q >> 2, mh = (q >> 1) & 1, term = q & 1;
        const int r    = mt * 32 + mh * 16 + (lane >> 2);
        const int k0   = ks * 16 + (lane & 3) * 2;

        const float w00 = W[(size_t)(kbase + k0)     * 256 + r];
        const float w01 = W[(size_t)(kbase + k0 + 1) * 256 + r];
        const float w10 = W[(size_t)(kbase + k0 + 8) * 256 + r];
        const float w11 = W[(size_t)(kbase + k0 + 9) * 256 + r];
        const float v00 = W[(size_t)(kbase + k0)     * 256 + r + 8];
        const float v01 = W[(size_t)(kbase + k0 + 1) * 256 + r + 8];
        const float v10 = W[(size_t)(kbase + k0 + 8) * 256 + r + 8];
        const float v11 = W[(size_t)(kbase + k0 + 9) * 256 + r + 8];

        uint4 o;
        o.x = pk_term(w00, w01, term);
        o.y = pk_term(v00, v01, term);
        o.z = pk_term(w10, w11, term);
        o.w = pk_term(v10, v11, term);
        g_Wfrag[((size_t)g * 8 + mt) * 256 + q * 32 + lane] = o;
    }
}

// ---------------- main kernel: 1 batch/CTA, 2 CTAs/SM, A pipelined per k16 ----------------
__global__ __launch_bounds__(THREADS, 2) void cin_mma_kernel(
    const float* __restrict__ x,
    const float* __restrict__ b0, const float* __restrict__ b1, const float* __restrict__ b2,
    const float* __restrict__ fcW, const float* __restrict__ fcb,
    float* __restrict__ out)
{
    extern __shared__ unsigned char smem[];
    const uint32_t sbase = smem_u32(smem);
    float* xs  = (float*)(smem + XS_OFF);
    float* hs  = (float*)(smem + HS_OFF);
    float* red = (float*)(smem + RED_OFF);

    const int tid = threadIdx.x, wid = tid >> 5, lane = tid & 31;
    const int B = blockIdx.x;
    const int mt = wid;

    // B ldmatrix lane addressing
    const int brl  = ((lane >> 4) << 3) + (lane & 7);
    const int bk16 = ((lane >> 3) & 1) * 16;

    // z-build mapping
    const int brow = tid >> 2;
    const int seg  = (tid & 3) * 8;
    const float* xvb = xs + brow;
    const float* biasl[3] = {b0, b1, b2};

    // stage x into padded xs (stride 65)
    #pragma unroll
    for (int i = 0; i < 2; ++i) {
        const int idx = tid + i * 256;
        const float4 v = ((const float4*)(x + (size_t)B * 2048))[idx];
        const int f = idx * 4;
        float* dp = xs + (f >> 6) * 65 + (f & 63);
        dp[0] = v.x; dp[1] = v.y; dp[2] = v.z; dp[3] = v.w;
    }
    __syncthreads();

    float fc_acc = 0.0f;
    const int r0 = lane >> 2;

    for (int layer = 0; layer < 3; ++layer) {
        const int nch = (layer == 0) ? 32 : 128;
        const int g0  = (layer == 0) ? 0 : ((layer == 1) ? 32 : 160);
        const float* hvb = (layer == 0) ? (xs + brow) : (hs + brow);

        float acc[2][8][4];
        #pragma unroll
        for (int a = 0; a < 2; ++a)
            #pragma unroll
            for (int j = 0; j < 8; ++j)
                #pragma unroll
                for (int e = 0; e < 4; ++e) acc[a][j][e] = 0.0f;

        auto buildB = [&](int cc, int buf) {
            const int m  = (layer == 0) ? cc : (cc >> 2);
            const int nb = (layer == 0) ? 0 : ((cc & 3) * 32);
            const float xv = xvb[m * 65];
            uint32_t hpk[4], lpk[4];
            #pragma unroll
            for (int q = 0; q < 4; ++q) {
                const float p0 = xv * hvb[(nb + seg + 2 * q) * 65];
                const float p1 = xv * hvb[(nb + seg + 2 * q + 1) * 65];
                const __nv_bfloat16 h0 = __float2bfloat16(p0), h1 = __float2bfloat16(p1);
                hpk[q] = (uint32_t)__bfloat16_as_ushort(h0) |
                         ((uint32_t)__bfloat16_as_ushort(h1) << 16);
                lpk[q] = pkbf(p0 - __bfloat162float(h0), p1 - __bfloat162float(h1));
            }
            unsigned char* bbs = smem + BBUF_OFF + buf * 8192;
            const uint32_t offh = brow * 128 + seg * 2;
            *(uint4*)(bbs + sw128(offh))      = make_uint4(hpk[0], hpk[1], hpk[2], hpk[3]);
            *(uint4*)(bbs + sw128(offh + 64)) = make_uint4(lpk[0], lpk[1], lpk[2], lpk[3]);
        };

        // load the 4 A fragments (mh x term) for (chunk, ks)
        auto loadA = [&](uint4* Aq, int chunk, int ks) {
            const uint4* __restrict__ P =
                g_Wfrag + ((size_t)chunk * 8 + mt) * 256 + ks * 128 + lane;
            #pragma unroll
            for (int q = 0; q < 4; ++q) Aq[q] = P[q * 32];
        };

        // 48 HMMA for one k16 slice
        auto computeKs = [&](const uint4* Aq, uint32_t bbse, int ks) {
            #pragma unroll
            for (int jj = 0; jj < 4; ++jj) {
                const uint32_t boff = (uint32_t)(jj * 16 + brl) * 128 + 32 * ks + bk16;
                uint32_t Bh[4], Bl[4];
                ldsm4(Bh, bbse + sw128(boff));
                ldsm4(Bl, bbse + sw128(boff + 64));
                #pragma unroll
                for (int mh = 0; mh < 2; ++mh) {
                    #pragma unroll
                    for (int jq = 0; jq < 2; ++jq) {
                        float* cc2 = acc[mh][2 * jj + jq];
                        mma16816_u4(cc2, Aq[mh * 2 + 0], Bh + 2 * jq);  // hi*hi
                        mma16816_u4(cc2, Aq[mh * 2 + 0], Bl + 2 * jq);  // hi*lo
                        mma16816_u4(cc2, Aq[mh * 2 + 1], Bh + 2 * jq);  // lo*hi
                    }
                }
            }
        };

        uint4 Acur[4], Anext[4];
        buildB(0, 0);
        loadA(Acur, g0, 0);
        __syncthreads();

        for (int c = 0; c < nch; ++c) {
            const int buf = c & 1;
            const uint32_t bbse = sbase + BBUF_OFF + buf * 8192;
            const int cn = (c + 1 < nch) ? c + 1 : c;   // clamp (harmless reload on last)

            loadA(Anext, g0 + c, 1);          // ks=1 of this chunk (shadowed by ks0 compute)
            if (c + 1 < nch) buildB(c + 1, buf ^ 1);
            computeKs(Acur, bbse, 0);
            loadA(Acur, g0 + cn, 0);          // ks=0 of next chunk (shadowed by ks1 compute)
            computeKs(Anext, bbse, 1);
            __syncthreads();                  // publish B buf^1
        }

        // ---- epilogue ----
        const float* bl = biasl[layer];
        const int fcbase = (layer == 2) ? 256 : layer * 128;
        const bool do_fc = (layer == 2) || (mt < 4);
        float bias4[4], fw4[4];
        #pragma unroll
        for (int rr = 0; rr < 4; ++rr) {
            const int row = mt * 32 + rr * 8 + r0;
            bias4[rr] = bl[row];
            fw4[rr] = do_fc ? fcW[fcbase + row] : 0.0f;
        }
        #pragma unroll
        for (int mh = 0; mh < 2; ++mh) {
            #pragma unroll
            for (int j = 0; j < 8; ++j) {
                #pragma unroll
                for (int e = 0; e < 4; ++e) {
                    const int rr = mh * 2 + (e >> 1);
                    const float v = fmaxf(acc[mh][j][e] + bias4[rr], 0.0f);
                    if (do_fc) {
                        fc_acc += fw4[rr] * v;
                    } else {
                        const int row = mt * 32 + mh * 16 + (e >> 1) * 8 + r0;
                        const int d   = 8 * j + 2 * (lane & 3) + (e & 1);
                        hs[(row - 128) * 65 + d] = v;
                    }
                }
            }
        }
        __syncthreads();
    }

    // final reduction (single batch)
    #pragma unroll
    for (int off = 16; off > 0; off >>= 1)
        fc_acc += __shfl_xor_sync(0xffffffffu, fc_acc, off);
    if (lane == 0) red[wid] = fc_acc;
    __syncthreads();
    if (tid == 0) {
        float s = 0.0f;
        #pragma unroll
        for (int w = 0; w < 8; ++w) s += red[w];
        out[B] = s + fcb[0];
    }
}

extern "C" void kernel_launch(void* const* d_in, const int* in_sizes, int n_in,
                              void* d_out, int out_size) {
    const float* x   = (const float*)d_in[0];
    const float* W0  = (const float*)d_in[1];
    const float* b0  = (const float*)d_in[2];
    const float* W1  = (const float*)d_in[3];
    const float* b1  = (const float*)d_in[4];
    const float* W2  = (const float*)d_in[5];
    const float* b2  = (const float*)d_in[6];
    const float* fcW = (const float*)d_in[7];
    const float* fcb = (const float*)d_in[8];
    float* out = (float*)d_out;

    cudaFuncSetAttribute(cin_mma_kernel, cudaFuncAttributeMaxDynamicSharedMemorySize, SMEM_BYTES);
    prep_kernel<<<NCHUNKS_TOT, 512>>>(W0, W1, W2);
    cin_mma_kernel<<<1024, THREADS, SMEM_BYTES>>>(x, b0, b1, b2, fcW, fcb, out);
}